// round 15
// baseline (speedup 1.0000x reference)
#include <cuda_runtime.h>
#include <stdint.h>

// ChannelPair2D: out[p, k] = x[p, i_k] * x[p, j_k], (i,j) i<j row-major triu.
// C=64 -> 2016 pairs, 65536 pixels. HBM-write-bound (~504 MiB out).
//
// R13 = R10 (identity thread->quad mapping, contiguous 512B warp stores,
// outer unroll-1 pixel loop, short divergent arms, meta-in-regs) +
//   - vectorized replica build: register blends + STS.128 instead of
//     3072 scalar LDS/STS per block  (L1 setup work ~4x down)
//   - PPB=16: halves per-block fixed overhead.

#define C_CH  64
#define NPAIR 2016
#define NQ    504               // NPAIR/4 quads
#define TPB   256
#define PPB   16                // pixels per block
#define PLANE (PPB * C_CH)      // floats per replica plane (1024)

// ---------------- compile-time tables (IDENTITY order: slot q = quad q) -----
struct MetaTab  { unsigned v[2 * TPB]; };
struct PairTab  { uint2    v[2 * TPB]; };

constexpr int off_of(int i) { return i * (127 - i) / 2; }

constexpr MetaTab build_meta() {
    MetaTab t{};
    for (int s = 0; s < 2 * TPB; ++s) t.v[s] = 0u;
    for (int q = 0; q < NQ; ++q) {
        int k = 4 * q, i = 0;
        while (off_of(i + 1) <= k) ++i;
        int j = i + 1 + (k - off_of(i));
        if (j + 3 <= 63) {
            // fast: bit31 | xi float-idx [0:8) | shifted-vec float-idx [8:24)
            t.v[q] = 0x80000000u
                   | (unsigned)i
                   | ((unsigned)((j & 3) * PLANE + (j & ~3)) << 8);
        }
    }
    return t;
}

constexpr PairTab build_pairs() {
    PairTab t{};
    for (int s = 0; s < 2 * TPB; ++s) t.v[s] = uint2{0u, 0u};
    for (int q = 0; q < NQ; ++q) {
        int k = 4 * q, i = 0;
        while (off_of(i + 1) <= k) ++i;
        int j = i + 1 + (k - off_of(i));
        unsigned b[8] = {0,0,0,0,0,0,0,0};
        int ii = i, jj = j;
        for (int e = 0; e < 4; ++e) {
            b[2*e]   = (unsigned)ii;
            b[2*e+1] = (unsigned)jj;
            ++jj; if (jj > 63) { ++ii; jj = ii + 1; }
        }
        t.v[q].x = b[0] | (b[1] << 8) | (b[2] << 16) | (b[3] << 24);
        t.v[q].y = b[4] | (b[5] << 8) | (b[6] << 16) | (b[7] << 24);
    }
    return t;
}

__device__ const MetaTab g_meta  = build_meta();
__device__ const PairTab g_pairs = build_pairs();

// ---------------- kernel ----------------
__global__ __launch_bounds__(TPB, 8)
void channelpair_kernel(const float* __restrict__ x,
                        float* __restrict__ out,
                        int npix) {
    // Shifted replicas: plane s holds x_p[c+s]; fast path reads x[j..j+3] as
    // one aligned LDS.128 at plane j&3, col j&~3.
    __shared__ __align__(16) float Bf[4 * PLANE];   // 16 KB

    const int tid  = threadIdx.x;
    const int pix0 = blockIdx.x * PPB;

    // Thread's two quads: q0 = tid (always < NQ), q1 = tid + 256 (may be >= NQ).
    const unsigned m0 = g_meta.v[tid];
    const unsigned m1 = g_meta.v[tid + TPB];
    const bool     a1 = (tid + TPB) < NQ;

    // Plane 0: PPB*64 floats = 256 float4 = exactly TPB loads; keep own quad.
    float4 v0;
    {
        const float4* src = (const float4*)(x + (size_t)pix0 * C_CH);
        const int pix = pix0 + (tid >> 4);              // 16 float4 per pixel
        v0 = (pix < npix) ? src[tid] : make_float4(0.f, 0.f, 0.f, 0.f);
        ((float4*)Bf)[tid] = v0;
    }
    __syncthreads();

    // Replica planes 1..3 via register blends (1 LDS.128 + 3 STS.128/thread).
    // Window slots whose shifted source crosses x[63] are never read by the
    // fast path (it requires j+3 <= 63), so no clamping is needed.
    {
        const int nidx = (tid < TPB - 1) ? tid + 1 : tid;   // avoid cross-plane race
        const float4 v1 = ((const float4*)Bf)[nidx];
        float4 w;
        float4* dst = (float4*)Bf + TPB + tid;   // plane 1, same (p,c4) slot
        w.x = v0.y; w.y = v0.z; w.z = v0.w; w.w = v1.x;   // s=1
        dst[0] = w;
        w.x = v0.z; w.y = v0.w; w.z = v1.x; w.w = v1.y;   // s=2
        dst[TPB] = w;
        w.x = v0.w; w.y = v1.x; w.z = v1.y; w.w = v1.z;   // s=3
        dst[2 * TPB] = w;
    }
    __syncthreads();

    // Decode once (register-resident).
    const bool f0  = (m0 >> 31) != 0;
    const bool f1  = (m1 >> 31) != 0;
    const int  xi0 = (int)(m0 & 0xFFu);
    const int  sv0 = (int)((m0 >> 8) & 0xFFFFu);
    const int  xi1 = (int)(m1 & 0xFFu);
    const int  sv1 = (int)((m1 >> 8) & 0xFFFFu);

    float4* o0 = (float4*)out + (size_t)pix0 * NQ + tid;
    float4* o1 = o0 + TPB;

    const int rem = npix - pix0;
    const int pc  = rem >= PPB ? PPB : rem;

    // Outer pixel loop: whole block writes one pixel's contiguous 8 KB per
    // iteration; each warp's stores span a contiguous 512B range.
    #pragma unroll 1
    for (int p = 0; p < pc; ++p) {
        const int    off = p * C_CH;          // pixel offset within each plane
        const float* xv  = Bf + off;          // plane-0 view for this pixel

        // ---- quad q0 = tid ----
        {
            float4 r;
            if (f0) {
                const float  xi = xv[xi0];
                const float4 v  = *(const float4*)(Bf + sv0 + off);
                r.x = xi * v.x; r.y = xi * v.y; r.z = xi * v.z; r.w = xi * v.w;
            } else {
                const uint2 d = __ldg(&g_pairs.v[tid]);       // L1-resident
                const unsigned z = d.x, w = d.y;
                r.x = xv[z & 255u]         * xv[(z >> 8) & 255u];
                r.y = xv[(z >> 16) & 255u] * xv[z >> 24];
                r.z = xv[w & 255u]         * xv[(w >> 8) & 255u];
                r.w = xv[(w >> 16) & 255u] * xv[w >> 24];
            }
            o0[(size_t)p * NQ] = r;
        }
        // ---- quad q1 = tid + 256 ----
        if (a1) {
            float4 r;
            if (f1) {
                const float  xi = xv[xi1];
                const float4 v  = *(const float4*)(Bf + sv1 + off);
                r.x = xi * v.x; r.y = xi * v.y; r.z = xi * v.z; r.w = xi * v.w;
            } else {
                const uint2 d = __ldg(&g_pairs.v[tid + TPB]); // L1-resident
                const unsigned z = d.x, w = d.y;
                r.x = xv[z & 255u]         * xv[(z >> 8) & 255u];
                r.y = xv[(z >> 16) & 255u] * xv[z >> 24];
                r.z = xv[w & 255u]         * xv[(w >> 8) & 255u];
                r.w = xv[(w >> 16) & 255u] * xv[w >> 24];
            }
            o1[(size_t)p * NQ] = r;
        }
    }
}

extern "C" void kernel_launch(void* const* d_in, const int* in_sizes, int n_in,
                              void* d_out, int out_size) {
    const float* x = (const float*)d_in[0];
    float* out = (float*)d_out;

    const int npix = in_sizes[0] / C_CH;            // 65536
    const int nblk = (npix + PPB - 1) / PPB;        // 4096

    channelpair_kernel<<<nblk, TPB>>>(x, out, npix);
}

// round 16
// speedup vs baseline: 1.0499x; 1.0499x over previous
#include <cuda_runtime.h>
#include <stdint.h>

// ChannelPair2D: out[p, k] = x[p, i_k] * x[p, j_k], (i,j) i<j row-major triu.
// C=64 -> 2016 pairs, 65536 pixels. HBM-write-bound (~504 MiB out).
//
// R16: identity thread->quad mapping (contiguous 512B warp stores) + UNIFORM
// branchless inner body: every quad (fast or row-wrapping) computed as a
// two-window blend  r[e] = sel(e)? x[i0]*A[e] : x[i0+1]*B[e], with A,B
// aligned LDS.128 from shifted replicas and (x[i0],x[i0+1]) one LDS.64.
// Kills the per-warp fast+boundary divergence that kept L1 at 90%.
// Only quads 15 and 503 (3-row spans) use a scalar gather (2 lanes total).

#define C_CH  64
#define NPAIR 2016
#define NQ    504               // NPAIR/4 quads
#define TPB   256
#define PPB   8                 // pixels per block
#define PLANE (PPB * C_CH)      // floats per replica plane (512)

// ---------------- compile-time tables (IDENTITY order: slot q = quad q) -----
struct MetaTab { uint2 v[2 * TPB]; };
struct PairTab { uint2 v[2 * TPB]; };

constexpr int off_of(int i) { return i * (127 - i) / 2; }

constexpr MetaTab build_meta() {
    MetaTab t{};
    for (int s = 0; s < 2 * TPB; ++s) t.v[s] = uint2{0u, 0u};
    for (int q = 0; q < NQ; ++q) {
        int k = 4 * q, i0 = 0;
        while (off_of(i0 + 1) <= k) ++i0;
        int j0 = i0 + 1 + (k - off_of(i0));
        int c0 = 64 - j0; if (c0 > 4) c0 = 4;          // elems taken from row i0
        bool special = (q == 15 || q == 503);          // 3-row / negative base

        int sx   = i0 & 1;
        int encX = sx * PLANE + (i0 - sx);             // LDS.64 -> x[i0],x[i0+1]
        int encA = (j0 & 3) * PLANE + (j0 & ~3);       // window at j0
        int fB   = (c0 == 4 || special) ? j0 : (i0 + 2 - c0);
        int encB = (fB & 3) * PLANE + (fB & ~3);       // window for wrapped elems

        t.v[q].x = (special ? 0x80000000u : 0u)
                 | ((unsigned)c0 << 28)
                 | ((unsigned)encA << 11)
                 | (unsigned)encX;
        t.v[q].y = (unsigned)encB;
    }
    return t;
}

constexpr PairTab build_pairs() {
    PairTab t{};
    for (int s = 0; s < 2 * TPB; ++s) t.v[s] = uint2{0u, 0u};
    for (int q = 0; q < NQ; ++q) {
        int k = 4 * q, i = 0;
        while (off_of(i + 1) <= k) ++i;
        int j = i + 1 + (k - off_of(i));
        unsigned b[8] = {0,0,0,0,0,0,0,0};
        int ii = i, jj = j;
        for (int e = 0; e < 4; ++e) {
            b[2*e]   = (unsigned)ii;
            b[2*e+1] = (unsigned)jj;
            ++jj; if (jj > 63) { ++ii; jj = ii + 1; }
        }
        t.v[q].x = b[0] | (b[1] << 8) | (b[2] << 16) | (b[3] << 24);
        t.v[q].y = b[4] | (b[5] << 8) | (b[6] << 16) | (b[7] << 24);
    }
    return t;
}

__device__ const MetaTab g_meta  = build_meta();
__device__ const PairTab g_pairs = build_pairs();

// ---------------- kernel ----------------
__global__ __launch_bounds__(TPB)
void channelpair_kernel(const float* __restrict__ x,
                        float* __restrict__ out,
                        int npix) {
    // Shifted replicas: plane s holds x_p[c+s]; window read at float-base f =
    // one aligned LDS.128 at plane f&3, col f&~3 giving x[f..f+3].
    __shared__ __align__(16) float Bf[4 * PLANE];   // 8 KB

    const int tid  = threadIdx.x;
    const int pix0 = blockIdx.x * PPB;

    const uint2 m0 = g_meta.v[tid];
    const uint2 m1 = g_meta.v[tid + TPB];
    const bool  act1 = (tid + TPB) < NQ;

    // Plane 0: PPB*64 floats = 128 float4 loads (threads 0..127), keep in reg.
    float4 v0 = make_float4(0.f, 0.f, 0.f, 0.f);
    if (tid < PPB * (C_CH / 4)) {
        const float4* src = (const float4*)(x + (size_t)pix0 * C_CH);
        const int pix = pix0 + (tid >> 4);            // 16 float4 per pixel
        v0 = (pix < npix) ? src[tid] : make_float4(0.f, 0.f, 0.f, 0.f);
        ((float4*)Bf)[tid] = v0;
    }
    __syncthreads();

    // Replica planes 1..3 via register blends (1 LDS.128 + 3 STS.128/thread).
    // Slots whose shifted source crosses x[63] hold garbage that is never
    // selected by the blend (all selected reads proven in-range).
    if (tid < PPB * (C_CH / 4)) {
        const int nidx = (tid < PPB * (C_CH / 4) - 1) ? tid + 1 : tid;
        const float4 v1 = ((const float4*)Bf)[nidx];
        float4 w;
        float4* dst = (float4*)Bf + (PLANE / 4) + tid;
        w.x = v0.y; w.y = v0.z; w.z = v0.w; w.w = v1.x;   // s=1
        dst[0] = w;
        w.x = v0.z; w.y = v0.w; w.z = v1.x; w.w = v1.y;   // s=2
        dst[PLANE / 4] = w;
        w.x = v0.w; w.y = v1.x; w.z = v1.y; w.w = v1.z;   // s=3
        dst[2 * (PLANE / 4)] = w;
    }
    __syncthreads();

    // Decode once (register-resident).
    const int  xX0 = (int)(m0.x & 0x7FFu);
    const int  xA0 = (int)((m0.x >> 11) & 0x7FFu);
    const int  xB0 = (int)(m0.y & 0x7FFu);
    const int  c00 = (int)((m0.x >> 28) & 7u);
    const bool sp0 = (m0.x >> 31) != 0;
    const bool s00 = c00 > 0, s01 = c00 > 1, s02 = c00 > 2, s03 = c00 > 3;

    const int  xX1 = (int)(m1.x & 0x7FFu);
    const int  xA1 = (int)((m1.x >> 11) & 0x7FFu);
    const int  xB1 = (int)(m1.y & 0x7FFu);
    const int  c01 = (int)((m1.x >> 28) & 7u);
    const bool sp1 = (m1.x >> 31) != 0;
    const bool s10 = c01 > 0, s11 = c01 > 1, s12 = c01 > 2, s13 = c01 > 3;

    float4* o0 = (float4*)out + (size_t)pix0 * NQ + tid;
    float4* o1 = o0 + TPB;

    const int rem = npix - pix0;
    const int pc  = rem >= PPB ? PPB : rem;

    // Outer pixel loop: whole block writes one pixel's contiguous 8 KB per
    // iteration; each warp's stores span a contiguous 512B range.
    #pragma unroll 1
    for (int p = 0; p < pc; ++p) {
        const int    off = p * C_CH;
        const float* xv  = Bf + off;

        // ---- quad q0 = tid ----
        {
            float4 r;
            if (!sp0) {
                const float2 xab = *(const float2*)(Bf + xX0 + off);
                const float4 va  = *(const float4*)(Bf + xA0 + off);
                const float4 vb  = *(const float4*)(Bf + xB0 + off);
                r.x = (s00 ? xab.x : xab.y) * (s00 ? va.x : vb.x);
                r.y = (s01 ? xab.x : xab.y) * (s01 ? va.y : vb.y);
                r.z = (s02 ? xab.x : xab.y) * (s02 ? va.z : vb.z);
                r.w = (s03 ? xab.x : xab.y) * (s03 ? va.w : vb.w);
            } else {
                const uint2 d = __ldg(&g_pairs.v[tid]);
                const unsigned z = d.x, w = d.y;
                r.x = xv[z & 255u]         * xv[(z >> 8) & 255u];
                r.y = xv[(z >> 16) & 255u] * xv[z >> 24];
                r.z = xv[w & 255u]         * xv[(w >> 8) & 255u];
                r.w = xv[(w >> 16) & 255u] * xv[w >> 24];
            }
            o0[(size_t)p * NQ] = r;
        }
        // ---- quad q1 = tid + 256 ----
        if (act1) {
            float4 r;
            if (!sp1) {
                const float2 xab = *(const float2*)(Bf + xX1 + off);
                const float4 va  = *(const float4*)(Bf + xA1 + off);
                const float4 vb  = *(const float4*)(Bf + xB1 + off);
                r.x = (s10 ? xab.x : xab.y) * (s10 ? va.x : vb.x);
                r.y = (s11 ? xab.x : xab.y) * (s11 ? va.y : vb.y);
                r.z = (s12 ? xab.x : xab.y) * (s12 ? va.z : vb.z);
                r.w = (s13 ? xab.x : xab.y) * (s13 ? va.w : vb.w);
            } else {
                const uint2 d = __ldg(&g_pairs.v[tid + TPB]);
                const unsigned z = d.x, w = d.y;
                r.x = xv[z & 255u]         * xv[(z >> 8) & 255u];
                r.y = xv[(z >> 16) & 255u] * xv[z >> 24];
                r.z = xv[w & 255u]         * xv[(w >> 8) & 255u];
                r.w = xv[(w >> 16) & 255u] * xv[w >> 24];
            }
            o1[(size_t)p * NQ] = r;
        }
    }
}

extern "C" void kernel_launch(void* const* d_in, const int* in_sizes, int n_in,
                              void* d_out, int out_size) {
    const float* x = (const float*)d_in[0];
    float* out = (float*)d_out;

    const int npix = in_sizes[0] / C_CH;            // 65536
    const int nblk = (npix + PPB - 1) / PPB;        // 8192

    channelpair_kernel<<<nblk, TPB>>>(x, out, npix);
}

// round 17
// speedup vs baseline: 1.0597x; 1.0093x over previous
#include <cuda_runtime.h>
#include <stdint.h>

// ChannelPair2D: out[p, k] = x[p, i_k] * x[p, j_k], (i,j) i<j row-major triu.
// C=64 -> 2016 pairs, 65536 pixels. HBM-write-bound (~504 MiB out).
//
// R17: identity thread->quad mapping (contiguous 512B warp stores) + minimal
// always-path (LDS.32 xi + LDS.128 window + 4 FMUL + STG.128) + PREDICATED
// sparse wrap-arm: only the 2-4 row-wrapping lanes per warp load x[i0+1] and
// a second window, then overwrite elements e >= c0. Quads 15 & 503 (negative
// base / 3-row span) use a scalar gather (2 lanes total per block).

#define C_CH  64
#define NPAIR 2016
#define NQ    504               // NPAIR/4 quads
#define TPB   256
#define PPB   8                 // pixels per block
#define PLANE (PPB * C_CH)      // floats per replica plane (512)

// ---------------- compile-time tables (IDENTITY order: slot q = quad q) -----
struct MetaTab { unsigned v[2 * TPB]; };
struct PairTab { uint2    v[2 * TPB]; };

constexpr int off_of(int i) { return i * (127 - i) / 2; }

// meta: [0:6) i0 | [6:17) encA | [17:28) encB | [28:30) c0-1 | b30 wrap | b31 special
constexpr MetaTab build_meta() {
    MetaTab t{};
    for (int s = 0; s < 2 * TPB; ++s) t.v[s] = 0u;
    for (int q = 0; q < NQ; ++q) {
        int k = 4 * q, i0 = 0;
        while (off_of(i0 + 1) <= k) ++i0;
        int j0 = i0 + 1 + (k - off_of(i0));
        int c0 = 64 - j0; if (c0 > 4) c0 = 4;           // elems from row i0 (1..4)
        bool special = (q == 15 || q == 503);           // base<0 / 3-row span
        bool wrap    = (c0 < 4) && !special;

        int encA = (j0 & 3) * PLANE + (j0 & ~3);        // window x[j0..j0+3]
        int fB   = wrap ? (i0 + 2 - c0) : j0;           // window x[fB..fB+3]
        int encB = (fB & 3) * PLANE + (fB & ~3);

        t.v[q] = (unsigned)i0
               | ((unsigned)encA << 6)
               | ((unsigned)encB << 17)
               | ((unsigned)(c0 - 1) << 28)
               | ((unsigned)(wrap ? 1 : 0) << 30)
               | ((unsigned)(special ? 1 : 0) << 31);
    }
    return t;
}

constexpr PairTab build_pairs() {
    PairTab t{};
    for (int s = 0; s < 2 * TPB; ++s) t.v[s] = uint2{0u, 0u};
    for (int q = 0; q < NQ; ++q) {
        int k = 4 * q, i = 0;
        while (off_of(i + 1) <= k) ++i;
        int j = i + 1 + (k - off_of(i));
        unsigned b[8] = {0,0,0,0,0,0,0,0};
        int ii = i, jj = j;
        for (int e = 0; e < 4; ++e) {
            b[2*e]   = (unsigned)ii;
            b[2*e+1] = (unsigned)jj;
            ++jj; if (jj > 63) { ++ii; jj = ii + 1; }
        }
        t.v[q].x = b[0] | (b[1] << 8) | (b[2] << 16) | (b[3] << 24);
        t.v[q].y = b[4] | (b[5] << 8) | (b[6] << 16) | (b[7] << 24);
    }
    return t;
}

__device__ const MetaTab g_meta  = build_meta();
__device__ const PairTab g_pairs = build_pairs();

// ---------------- kernel ----------------
__global__ __launch_bounds__(TPB, 8)
void channelpair_kernel(const float* __restrict__ x,
                        float* __restrict__ out,
                        int npix) {
    // Shifted replicas: plane s holds x_p[c+s]; window read at float-base f =
    // one aligned LDS.128 at plane f&3, col f&~3 giving x[f..f+3].
    __shared__ __align__(16) float Bf[4 * PLANE];   // 8 KB

    const int tid  = threadIdx.x;
    const int pix0 = blockIdx.x * PPB;

    const unsigned m0 = g_meta.v[tid];
    const unsigned m1 = g_meta.v[tid + TPB];
    const bool   act1 = (tid + TPB) < NQ;

    // Plane 0: PPB*64 floats = 128 float4 loads (threads 0..127), keep in reg.
    float4 v0 = make_float4(0.f, 0.f, 0.f, 0.f);
    if (tid < PPB * (C_CH / 4)) {
        const float4* src = (const float4*)(x + (size_t)pix0 * C_CH);
        const int pix = pix0 + (tid >> 4);            // 16 float4 per pixel
        v0 = (pix < npix) ? src[tid] : make_float4(0.f, 0.f, 0.f, 0.f);
        ((float4*)Bf)[tid] = v0;
    }
    __syncthreads();

    // Replica planes 1..3 via register blends (1 LDS.128 + 3 STS.128/thread).
    // Cross-row garbage slots exist only at window elements that the wrap/
    // special arms overwrite or never select.
    if (tid < PPB * (C_CH / 4)) {
        const int nidx = (tid < PPB * (C_CH / 4) - 1) ? tid + 1 : tid;
        const float4 v1 = ((const float4*)Bf)[nidx];
        float4 w;
        float4* dst = (float4*)Bf + (PLANE / 4) + tid;
        w.x = v0.y; w.y = v0.z; w.z = v0.w; w.w = v1.x;   // s=1
        dst[0] = w;
        w.x = v0.z; w.y = v0.w; w.z = v1.x; w.w = v1.y;   // s=2
        dst[PLANE / 4] = w;
        w.x = v0.w; w.y = v1.x; w.z = v1.y; w.w = v1.z;   // s=3
        dst[2 * (PLANE / 4)] = w;
    }
    __syncthreads();

    // Decode once (register-resident; one uint per slot).
    const int  i00  = (int)(m0 & 63u);
    const int  eA0  = (int)((m0 >> 6)  & 2047u);
    const int  eB0  = (int)((m0 >> 17) & 2047u);
    const int  c00  = (int)((m0 >> 28) & 3u) + 1;
    const bool wr0  = ((m0 >> 30) & 1u) != 0;
    const bool sp0  = (m0 >> 31) != 0;

    const int  i01  = (int)(m1 & 63u);
    const int  eA1  = (int)((m1 >> 6)  & 2047u);
    const int  eB1  = (int)((m1 >> 17) & 2047u);
    const int  c01  = (int)((m1 >> 28) & 3u) + 1;
    const bool wr1  = ((m1 >> 30) & 1u) != 0;
    const bool sp1  = (m1 >> 31) != 0;

    float4* o0 = (float4*)out + (size_t)pix0 * NQ + tid;
    float4* o1 = o0 + TPB;

    const int rem = npix - pix0;
    const int pc  = rem >= PPB ? PPB : rem;

    // Outer pixel loop: whole block writes one pixel's contiguous 8 KB per
    // iteration; each warp's stores span a contiguous 512B range.
    #pragma unroll 1
    for (int p = 0; p < pc; ++p) {
        const int    off = p * C_CH;
        const float* xv  = Bf + off;

        // ---- quad q0 = tid ----
        {
            const float  xi = xv[i00];
            const float4 va = *(const float4*)(Bf + eA0 + off);
            float4 r;
            r.x = xi * va.x; r.y = xi * va.y; r.z = xi * va.z; r.w = xi * va.w;
            if (wr0) {                       // sparse: 2-4 lanes per warp
                const float  xj = xv[i00 + 1];
                const float4 vb = *(const float4*)(Bf + eB0 + off);
                if (c00 <= 1) r.y = xj * vb.y;
                if (c00 <= 2) r.z = xj * vb.z;
                r.w = xj * vb.w;             // wrap implies c0 <= 3
            }
            if (sp0) {                       // 1 lane per block (q=15)
                const uint2 d = __ldg(&g_pairs.v[tid]);
                const unsigned z = d.x, w = d.y;
                r.x = xv[z & 255u]         * xv[(z >> 8) & 255u];
                r.y = xv[(z >> 16) & 255u] * xv[z >> 24];
                r.z = xv[w & 255u]         * xv[(w >> 8) & 255u];
                r.w = xv[(w >> 16) & 255u] * xv[w >> 24];
            }
            o0[(size_t)p * NQ] = r;
        }
        // ---- quad q1 = tid + 256 ----
        if (act1) {
            const float  xi = xv[i01];
            const float4 va = *(const float4*)(Bf + eA1 + off);
            float4 r;
            r.x = xi * va.x; r.y = xi * va.y; r.z = xi * va.z; r.w = xi * va.w;
            if (wr1) {
                const float  xj = xv[i01 + 1];
                const float4 vb = *(const float4*)(Bf + eB1 + off);
                if (c01 <= 1) r.y = xj * vb.y;
                if (c01 <= 2) r.z = xj * vb.z;
                r.w = xj * vb.w;
            }
            if (sp1) {                       // 1 lane per block (q=503)
                const uint2 d = __ldg(&g_pairs.v[tid + TPB]);
                const unsigned z = d.x, w = d.y;
                r.x = xv[z & 255u]         * xv[(z >> 8) & 255u];
                r.y = xv[(z >> 16) & 255u] * xv[z >> 24];
                r.z = xv[w & 255u]         * xv[(w >> 8) & 255u];
                r.w = xv[(w >> 16) & 255u] * xv[w >> 24];
            }
            o1[(size_t)p * NQ] = r;
        }
    }
}

extern "C" void kernel_launch(void* const* d_in, const int* in_sizes, int n_in,
                              void* d_out, int out_size) {
    const float* x = (const float*)d_in[0];
    float* out = (float*)d_out;

    const int npix = in_sizes[0] / C_CH;            // 65536
    const int nblk = (npix + PPB - 1) / PPB;        // 8192

    channelpair_kernel<<<nblk, TPB>>>(x, out, npix);
}